// round 2
// baseline (speedup 1.0000x reference)
#include <cuda_runtime.h>

#define B_  32
#define C_  512
#define HW_ 4096
#define N_  80

// Scratch: logits -> (in-place) attention weights. Static __device__ per allocation rules.
__device__ float g_att[(size_t)B_ * N_ * HW_];

// ---------------------------------------------------------------------------
// GEMM1: L[b, n, h] = sum_c feats[b, c, h] * W[n, c]
// grid: (HW/128, B), block 256. CTA tile: 80(n) x 128(h), KT=32.
// ---------------------------------------------------------------------------
__global__ __launch_bounds__(256) void gemm1_kernel(const float* __restrict__ feats,
                                                    const float* __restrict__ W) {
    const int b  = blockIdx.y;
    const int h0 = blockIdx.x * 128;

    __shared__ float Ws[32][81];   // [k][n]  stride 81 (odd) -> conflict-free T-stores
    __shared__ float Fs[32][132];  // [k][h]  stride 132 (mult of 4) -> aligned f4 stores

    const int tid = threadIdx.x;
    const int tx = tid & 15;
    const int ty = tid >> 4;

    float acc[5][8];
#pragma unroll
    for (int i = 0; i < 5; i++)
#pragma unroll
        for (int j = 0; j < 8; j++) acc[i][j] = 0.0f;

    const float* Fb = feats + (size_t)b * C_ * HW_;

    for (int k0 = 0; k0 < C_; k0 += 32) {
        // W tile: 80 n x 32 k = 640 float4 (transpose into Ws[k][n])
#pragma unroll
        for (int r = 0; r < 3; r++) {
            int linear = tid + r * 256;
            if (linear < 640) {
                int k4 = linear & 7;
                int n  = linear >> 3;
                float4 v = *(const float4*)(W + (size_t)n * C_ + k0 + k4 * 4);
                Ws[k4 * 4 + 0][n] = v.x;
                Ws[k4 * 4 + 1][n] = v.y;
                Ws[k4 * 4 + 2][n] = v.z;
                Ws[k4 * 4 + 3][n] = v.w;
            }
        }
        // F tile: 32 k-rows x 128 h, rows contiguous in h -> direct float4 stores
#pragma unroll
        for (int r = 0; r < 4; r++) {
            int linear = tid + r * 256;
            int h4 = linear & 31;
            int k  = linear >> 5;
            *(float4*)&Fs[k][h4 * 4] =
                *(const float4*)(Fb + (size_t)(k0 + k) * HW_ + h0 + h4 * 4);
        }
        __syncthreads();

#pragma unroll
        for (int k = 0; k < 32; k++) {
            float a[5], f[8];
#pragma unroll
            for (int i = 0; i < 5; i++) a[i] = Ws[k][i * 16 + ty];
#pragma unroll
            for (int j = 0; j < 8; j++) f[j] = Fs[k][j * 16 + tx];
#pragma unroll
            for (int i = 0; i < 5; i++)
#pragma unroll
                for (int j = 0; j < 8; j++) acc[i][j] = fmaf(a[i], f[j], acc[i][j]);
        }
        __syncthreads();
    }

    float* Lb = g_att + (size_t)b * N_ * HW_;
#pragma unroll
    for (int i = 0; i < 5; i++)
#pragma unroll
        for (int j = 0; j < 8; j++)
            Lb[(size_t)(i * 16 + ty) * HW_ + h0 + j * 16 + tx] = acc[i][j];
}

// ---------------------------------------------------------------------------
// Softmax over the HW axis, in place in g_att. grid: B*N rows, block 256.
// Each thread holds 16 values (4 x float4) in registers.
// ---------------------------------------------------------------------------
__global__ __launch_bounds__(256) void softmax_kernel() {
    float* row = g_att + (size_t)blockIdx.x * HW_;
    const int tid = threadIdx.x;
    __shared__ float sm[8];

    float4 v[4];
#pragma unroll
    for (int q = 0; q < 4; q++) v[q] = ((const float4*)row)[tid + q * 256];

    // block max
    float mx = -3.0e38f;
#pragma unroll
    for (int q = 0; q < 4; q++)
        mx = fmaxf(mx, fmaxf(fmaxf(v[q].x, v[q].y), fmaxf(v[q].z, v[q].w)));
#pragma unroll
    for (int o = 16; o; o >>= 1) mx = fmaxf(mx, __shfl_xor_sync(0xffffffffu, mx, o));
    if ((tid & 31) == 0) sm[tid >> 5] = mx;
    __syncthreads();
    mx = sm[0];
#pragma unroll
    for (int w = 1; w < 8; w++) mx = fmaxf(mx, sm[w]);
    __syncthreads();

    // exp + block sum
    float s = 0.0f;
#pragma unroll
    for (int q = 0; q < 4; q++) {
        v[q].x = expf(v[q].x - mx);
        v[q].y = expf(v[q].y - mx);
        v[q].z = expf(v[q].z - mx);
        v[q].w = expf(v[q].w - mx);
        s += (v[q].x + v[q].y) + (v[q].z + v[q].w);
    }
#pragma unroll
    for (int o = 16; o; o >>= 1) s += __shfl_xor_sync(0xffffffffu, s, o);
    if ((tid & 31) == 0) sm[tid >> 5] = s;
    __syncthreads();
    s = sm[0];
#pragma unroll
    for (int w = 1; w < 8; w++) s += sm[w];

    const float inv = 1.0f / s;
#pragma unroll
    for (int q = 0; q < 4; q++) {
        v[q].x *= inv; v[q].y *= inv; v[q].z *= inv; v[q].w *= inv;
        ((float4*)row)[tid + q * 256] = v[q];
    }
}

// ---------------------------------------------------------------------------
// GEMM2: out[b, n, c] = sum_h A[b, n, h] * feats[b, c, h]
// grid: (C/128, B), block 256. CTA tile: 80(n) x 128(c), K=HW staged in KT=32.
// Both operands are h(k)-contiguous -> float4 loads + transpose into smem.
// ---------------------------------------------------------------------------
__global__ __launch_bounds__(256) void gemm2_kernel(const float* __restrict__ feats,
                                                    float* __restrict__ out) {
    const int b  = blockIdx.y;
    const int c0 = blockIdx.x * 128;

    __shared__ float As[32][81];   // [k][n]  stride 81: conflict-free T-stores/reads
    __shared__ float Fs[32][129];  // [k][c]  stride 129 (odd): conflict-free T-stores

    const int tid = threadIdx.x;
    const int tx = tid & 15;
    const int ty = tid >> 4;

    float acc[5][8];
#pragma unroll
    for (int i = 0; i < 5; i++)
#pragma unroll
        for (int j = 0; j < 8; j++) acc[i][j] = 0.0f;

    const float* Ab = g_att + (size_t)b * N_ * HW_;
    const float* Fb = feats + (size_t)b * C_ * HW_;

    for (int k0 = 0; k0 < HW_; k0 += 32) {
        // A tile: 80 n x 32 k = 640 float4, transpose into As[k][n]
#pragma unroll
        for (int r = 0; r < 3; r++) {
            int linear = tid + r * 256;
            if (linear < 640) {
                int k4 = linear & 7;
                int n  = linear >> 3;
                float4 v = *(const float4*)(Ab + (size_t)n * HW_ + k0 + k4 * 4);
                As[k4 * 4 + 0][n] = v.x;
                As[k4 * 4 + 1][n] = v.y;
                As[k4 * 4 + 2][n] = v.z;
                As[k4 * 4 + 3][n] = v.w;
            }
        }
        // F tile: 128 c x 32 k = 1024 float4, transpose into Fs[k][c]
#pragma unroll
        for (int r = 0; r < 4; r++) {
            int linear = tid + r * 256;
            int k4 = linear & 7;
            int c  = linear >> 3;
            float4 v = *(const float4*)(Fb + (size_t)(c0 + c) * HW_ + k0 + k4 * 4);
            Fs[k4 * 4 + 0][c] = v.x;
            Fs[k4 * 4 + 1][c] = v.y;
            Fs[k4 * 4 + 2][c] = v.z;
            Fs[k4 * 4 + 3][c] = v.w;
        }
        __syncthreads();

#pragma unroll
        for (int k = 0; k < 32; k++) {
            float a[5], f[8];
#pragma unroll
            for (int i = 0; i < 5; i++) a[i] = As[k][i * 16 + ty];
#pragma unroll
            for (int j = 0; j < 8; j++) f[j] = Fs[k][j * 16 + tx];
#pragma unroll
            for (int i = 0; i < 5; i++)
#pragma unroll
                for (int j = 0; j < 8; j++) acc[i][j] = fmaf(a[i], f[j], acc[i][j]);
        }
        __syncthreads();
    }

    float* Ob = out + (size_t)b * N_ * C_;
#pragma unroll
    for (int i = 0; i < 5; i++)
#pragma unroll
        for (int j = 0; j < 8; j++)
            Ob[(size_t)(i * 16 + ty) * C_ + c0 + j * 16 + tx] = acc[i][j];
}

// ---------------------------------------------------------------------------
extern "C" void kernel_launch(void* const* d_in, const int* in_sizes, int n_in,
                              void* d_out, int out_size) {
    const float* feats = (const float*)d_in[0];  // [32, 512, 4096]
    const float* W     = (const float*)d_in[1];  // [80, 512]
    float* out         = (float*)d_out;          // [32, 80, 512]

    gemm1_kernel<<<dim3(HW_ / 128, B_), 256>>>(feats, W);
    softmax_kernel<<<B_ * N_, 256>>>();
    gemm2_kernel<<<dim3(C_ / 128, B_), 256>>>(feats, out);
}

// round 4
// speedup vs baseline: 3.5893x; 3.5893x over previous
#include <cuda_runtime.h>
#include <cuda_bf16.h>
#include <cstdint>

#define B_  32
#define C_  512
#define HW_ 4096
#define N_  80

// Scratch (__device__ globals per allocation rules)
__device__ float         g_logits[(size_t)B_ * N_ * HW_];
__device__ __nv_bfloat16 g_att_hi[(size_t)B_ * N_ * HW_];
__device__ __nv_bfloat16 g_att_lo[(size_t)B_ * N_ * HW_];

// ---------------------------------------------------------------------------
// helpers
// ---------------------------------------------------------------------------
__device__ __forceinline__ uint32_t smem_u32(const void* p) {
    uint32_t a;
    asm("{ .reg .u64 t; cvta.to.shared.u64 t, %1; cvt.u32.u64 %0, t; }" : "=r"(a) : "l"(p));
    return a;
}
__device__ __forceinline__ uint32_t swz(uint32_t off) { return off ^ ((off >> 3) & 0x70u); }
__device__ __forceinline__ void sts32(uint32_t addr, uint32_t v) {
    asm volatile("st.shared.b32 [%0], %1;" :: "r"(addr), "r"(v));
}
__device__ __forceinline__ uint32_t lds32(uint32_t addr) {
    uint32_t v;
    asm volatile("ld.shared.b32 %0, [%1];" : "=r"(v) : "r"(addr));
    return v;
}
__device__ __forceinline__ void ldmx4t(uint32_t* r, uint32_t addr) {
    asm volatile("ldmatrix.sync.aligned.m8n8.x4.trans.shared.b16 {%0,%1,%2,%3}, [%4];"
                 : "=r"(r[0]), "=r"(r[1]), "=r"(r[2]), "=r"(r[3]) : "r"(addr));
}
// D(f32) += A(bf16) * B(bf16), m16n8k16
__device__ __forceinline__ void mma16816(float* d, const uint32_t* a, const uint32_t* b) {
    asm volatile(
        "mma.sync.aligned.m16n8k16.row.col.f32.bf16.bf16.f32 "
        "{%0,%1,%2,%3}, {%4,%5,%6,%7}, {%8,%9}, {%0,%1,%2,%3};"
        : "+f"(d[0]), "+f"(d[1]), "+f"(d[2]), "+f"(d[3])
        : "r"(a[0]), "r"(a[1]), "r"(a[2]), "r"(a[3]), "r"(b[0]), "r"(b[1]));
}
// split two f32 -> packed bf16 hi pair / lo (residual) pair; low half = first value
__device__ __forceinline__ void split2(float f0, float f1, uint32_t& hi, uint32_t& lo) {
    asm("cvt.rn.bf16x2.f32 %0, %1, %2;" : "=r"(hi) : "f"(f1), "f"(f0));
    float h0 = __uint_as_float(hi << 16);
    float h1 = __uint_as_float(hi & 0xffff0000u);
    asm("cvt.rn.bf16x2.f32 %0, %1, %2;" : "=r"(lo) : "f"(f1 - h1), "f"(f0 - h0));
}

#define G1_BUF 53248u
#define G2_BUF 53248u

// ===========================================================================
// GEMM1: logits[b,n,h] = sum_c W[n,c] * feats[b,c,h]
//   mma M=n(80), N=h(128/CTA), K=c. 320 threads = 10 warps (5 m x 2 h).
//   smem buffer: Whi[80x64]@0 (10240), Wlo@10240,
//                Fhi halves [64c x 64h]@20480 (+8192), Flo@36864 (+8192)
// ===========================================================================
__global__ __launch_bounds__(320, 1) void gemm1_mma(const float* __restrict__ feats,
                                                    const float* __restrict__ W) {
    extern __shared__ __align__(1024) char smem[];
    const uint32_t sb = smem_u32(smem);
    const int tid = threadIdx.x, wid = tid >> 5, lane = tid & 31;
    const int g = lane >> 2, t = lane & 3;
    const int mw = wid % 5, hw = wid / 5;      // warp tile: m0=mw*16 (n), h half = hw*64
    const int m0 = mw * 16;
    const int b = blockIdx.y, hC = blockIdx.x * 128;

    const float* Fb = feats + (size_t)b * C_ * HW_;

    float acc[8][4];
#pragma unroll
    for (int i = 0; i < 8; i++)
#pragma unroll
        for (int j = 0; j < 4; j++) acc[i][j] = 0.0f;

    float2 wv[8];
    float fv0[13], fv1[13];

    auto ldg_tile = [&](int kb) {
        const int c0 = kb * 64;
#pragma unroll
        for (int it = 0; it < 8; it++) {
            int p = tid + it * 320, n = p >> 5, cp = p & 31;
            wv[it] = *(const float2*)(W + n * C_ + c0 + 2 * cp);
        }
#pragma unroll
        for (int it = 0; it < 13; it++) {
            int p = tid + it * 320;
            if (p < 4096) {
                int c = p >> 6, hp = p & 63;
                fv0[it] = Fb[(size_t)(c0 + c) * HW_ + hC + 2 * hp];
                fv1[it] = Fb[(size_t)(c0 + c) * HW_ + hC + 2 * hp + 1];
            }
        }
    };
    auto sts_tile = [&](uint32_t buf) {
#pragma unroll
        for (int it = 0; it < 8; it++) {
            int p = tid + it * 320, n = p >> 5, cp = p & 31;
            uint32_t hi, lo; split2(wv[it].x, wv[it].y, hi, lo);
            uint32_t off = swz((uint32_t)(n * 128 + cp * 4));
            sts32(buf + off, hi);
            sts32(buf + 10240u + off, lo);
        }
#pragma unroll
        for (int it = 0; it < 13; it++) {
            int p = tid + it * 320;
            if (p < 4096) {
                int c = p >> 6, hp = p & 63;
                uint32_t hi, lo; split2(fv0[it], fv1[it], hi, lo);
                uint32_t half = (uint32_t)(hp >> 5) * 8192u;
                uint32_t off = swz((uint32_t)(c * 128 + (hp & 31) * 4));
                sts32(buf + 20480u + half + off, hi);
                sts32(buf + 36864u + half + off, lo);
            }
        }
    };
    auto compute = [&](uint32_t buf) {
        const uint32_t Wh = buf, Wl = buf + 10240u;
        const uint32_t Fh = buf + 20480u + (uint32_t)hw * 8192u;
        const uint32_t Fl = buf + 36864u + (uint32_t)hw * 8192u;
#pragma unroll
        for (int ks = 0; ks < 4; ks++) {
            uint32_t ah[4], al[4];
#pragma unroll
            for (int q = 0; q < 4; q++) {
                uint32_t off = swz((uint32_t)((m0 + g + (q & 1) * 8) * 128 +
                                              ks * 32 + t * 4 + (q >> 1) * 16));
                ah[q] = lds32(Wh + off);
                al[q] = lds32(Wl + off);
            }
#pragma unroll
            for (int np = 0; np < 4; np++) {
                uint32_t rh[4], rl[4];
                uint32_t row = (uint32_t)(ks * 16 + (lane & 15));
                uint32_t colb = (uint32_t)((np * 16 + ((lane >> 4) << 3)) * 2);
                uint32_t off = swz(row * 128 + colb);
                ldmx4t(rh, Fh + off);
                ldmx4t(rl, Fl + off);
                mma16816(acc[2 * np],     ah, rh + 0);
                mma16816(acc[2 * np],     ah, rl + 0);
                mma16816(acc[2 * np],     al, rh + 0);
                mma16816(acc[2 * np + 1], ah, rh + 2);
                mma16816(acc[2 * np + 1], ah, rl + 2);
                mma16816(acc[2 * np + 1], al, rh + 2);
            }
        }
    };

    ldg_tile(0);
    sts_tile(sb);
    __syncthreads();
#pragma unroll 1
    for (int kb = 0; kb < 8; kb++) {
        if (kb + 1 < 8) ldg_tile(kb + 1);
        compute(sb + (uint32_t)(kb & 1) * G1_BUF);
        __syncthreads();
        if (kb + 1 < 8) {
            sts_tile(sb + (uint32_t)((kb + 1) & 1) * G1_BUF);
            __syncthreads();
        }
    }

    // epilogue: logits fp32 (n rows cover exactly 80, no masking)
#pragma unroll
    for (int nf = 0; nf < 8; nf++) {
        int h = hC + hw * 64 + nf * 8 + 2 * t;
        int n = m0 + g;
        float* p0 = g_logits + (size_t)(b * N_ + n) * HW_ + h;
        float* p1 = g_logits + (size_t)(b * N_ + n + 8) * HW_ + h;
        *(float2*)p0 = make_float2(acc[nf][0], acc[nf][1]);
        *(float2*)p1 = make_float2(acc[nf][2], acc[nf][3]);
    }
}

// ===========================================================================
// Softmax over HW, g_logits -> split bf16 att maps. grid B*N, block 256.
// ===========================================================================
__global__ __launch_bounds__(256) void softmax_split() {
    const size_t row = blockIdx.x;
    const float* rowp = g_logits + row * HW_;
    const int tid = threadIdx.x;
    __shared__ float sm[8];

    float4 v[4];
#pragma unroll
    for (int q = 0; q < 4; q++) v[q] = ((const float4*)rowp)[tid + q * 256];

    float mx = -3.0e38f;
#pragma unroll
    for (int q = 0; q < 4; q++)
        mx = fmaxf(mx, fmaxf(fmaxf(v[q].x, v[q].y), fmaxf(v[q].z, v[q].w)));
#pragma unroll
    for (int o = 16; o; o >>= 1) mx = fmaxf(mx, __shfl_xor_sync(0xffffffffu, mx, o));
    if ((tid & 31) == 0) sm[tid >> 5] = mx;
    __syncthreads();
    mx = sm[0];
#pragma unroll
    for (int w = 1; w < 8; w++) mx = fmaxf(mx, sm[w]);
    __syncthreads();

    float s = 0.0f;
#pragma unroll
    for (int q = 0; q < 4; q++) {
        v[q].x = expf(v[q].x - mx); v[q].y = expf(v[q].y - mx);
        v[q].z = expf(v[q].z - mx); v[q].w = expf(v[q].w - mx);
        s += (v[q].x + v[q].y) + (v[q].z + v[q].w);
    }
#pragma unroll
    for (int o = 16; o; o >>= 1) s += __shfl_xor_sync(0xffffffffu, s, o);
    if ((tid & 31) == 0) sm[tid >> 5] = s;
    __syncthreads();
    s = sm[0];
#pragma unroll
    for (int w = 1; w < 8; w++) s += sm[w];

    const float inv = 1.0f / s;
    uint32_t* hi_w = (uint32_t*)(g_att_hi + row * HW_);
    uint32_t* lo_w = (uint32_t*)(g_att_lo + row * HW_);
#pragma unroll
    for (int q = 0; q < 4; q++) {
        uint32_t h0, l0, h1, l1;
        split2(v[q].x * inv, v[q].y * inv, h0, l0);
        split2(v[q].z * inv, v[q].w * inv, h1, l1);
        int idx = (tid + q * 256) * 2;
        hi_w[idx] = h0; hi_w[idx + 1] = h1;
        lo_w[idx] = l0; lo_w[idx + 1] = l1;
    }
}

// ===========================================================================
// GEMM2: out[b,n,c] = sum_h att[b,n,h] * feats[b,c,h]
//   mma M=c(128/CTA), N=n(80), K=h. 256 threads = 8 warps (4 m x 2 n).
//   smem buffer: Fhi[128c x 64h]@0 (16384), Flo@16384,
//                Ahi att[80n x 64h]@32768 (10240), Alo@43008
// ===========================================================================
__global__ __launch_bounds__(256, 1) void gemm2_mma(const float* __restrict__ feats,
                                                    float* __restrict__ out) {
    extern __shared__ __align__(1024) char smem[];
    const uint32_t sb = smem_u32(smem);
    const int tid = threadIdx.x, wid = tid >> 5, lane = tid & 31;
    const int g = lane >> 2, t = lane & 3;
    const int mw = wid & 3, nw = wid >> 2;    // m0 = mw*32 (c), n0 = nw*40 (n)
    const int m0 = mw * 32, n0 = nw * 40;
    const int b = blockIdx.y, c0 = blockIdx.x * 128;

    const float* Fb = feats + (size_t)b * C_ * HW_;
    const __nv_bfloat16* AH = g_att_hi + (size_t)b * N_ * HW_;
    const __nv_bfloat16* AL = g_att_lo + (size_t)b * N_ * HW_;

    float acc[2][5][4];
#pragma unroll
    for (int i = 0; i < 2; i++)
#pragma unroll
        for (int j = 0; j < 5; j++)
#pragma unroll
            for (int k = 0; k < 4; k++) acc[i][j][k] = 0.0f;

    float2 av[16];
    uint32_t bhv[10], blv[10];

    auto ldg_tile = [&](int kb) {
        const int hk = kb * 64;
#pragma unroll
        for (int it = 0; it < 16; it++) {
            int p = tid + it * 256, c = p >> 5, hp = p & 31;
            av[it] = *(const float2*)(Fb + (size_t)(c0 + c) * HW_ + hk + 2 * hp);
        }
#pragma unroll
        for (int it = 0; it < 10; it++) {
            int p = tid + it * 256, n = p >> 5, w = p & 31;
            bhv[it] = ((const uint32_t*)(AH + (size_t)n * HW_ + hk))[w];
            blv[it] = ((const uint32_t*)(AL + (size_t)n * HW_ + hk))[w];
        }
    };
    auto sts_tile = [&](uint32_t buf) {
#pragma unroll
        for (int it = 0; it < 16; it++) {
            int p = tid + it * 256, c = p >> 5, hp = p & 31;
            uint32_t hi, lo; split2(av[it].x, av[it].y, hi, lo);
            uint32_t off = swz((uint32_t)(c * 128 + hp * 4));
            sts32(buf + off, hi);
            sts32(buf + 16384u + off, lo);
        }
#pragma unroll
        for (int it = 0; it < 10; it++) {
            int p = tid + it * 256, n = p >> 5, w = p & 31;
            uint32_t off = swz((uint32_t)(n * 128 + w * 4));
            sts32(buf + 32768u + off, bhv[it]);
            sts32(buf + 43008u + off, blv[it]);
        }
    };
    auto compute = [&](uint32_t buf) {
        const uint32_t Fh = buf, Fl = buf + 16384u;
        const uint32_t Bh = buf + 32768u, Bl = buf + 43008u;
#pragma unroll
        for (int ks = 0; ks < 4; ks++) {
            uint32_t ah[2][4], al[2][4];
#pragma unroll
            for (int mt = 0; mt < 2; mt++)
#pragma unroll
                for (int q = 0; q < 4; q++) {
                    uint32_t off = swz((uint32_t)((m0 + mt * 16 + g + (q & 1) * 8) * 128 +
                                                  ks * 32 + t * 4 + (q >> 1) * 16));
                    ah[mt][q] = lds32(Fh + off);
                    al[mt][q] = lds32(Fl + off);
                }
#pragma unroll
            for (int nf = 0; nf < 5; nf++) {
                uint32_t bh[2], bl[2];
#pragma unroll
                for (int q = 0; q < 2; q++) {
                    uint32_t off = swz((uint32_t)((n0 + nf * 8 + g) * 128 +
                                                  ks * 32 + t * 4 + q * 16));
                    bh[q] = lds32(Bh + off);
                    bl[q] = lds32(Bl + off);
                }
#pragma unroll
                for (int mt = 0; mt < 2; mt++) {
                    mma16816(acc[mt][nf], ah[mt], bh);
                    mma16816(acc[mt][nf], ah[mt], bl);
                    mma16816(acc[mt][nf], al[mt], bh);
                }
            }
        }
    };

    ldg_tile(0);
    sts_tile(sb);
    __syncthreads();
#pragma unroll 1
    for (int kb = 0; kb < 64; kb++) {
        if (kb + 1 < 64) ldg_tile(kb + 1);
        compute(sb + (uint32_t)(kb & 1) * G2_BUF);
        __syncthreads();
        if (kb + 1 < 64) {
            sts_tile(sb + (uint32_t)((kb + 1) & 1) * G2_BUF);
            __syncthreads();
        }
    }

    // epilogue: out[b, n, c]
#pragma unroll
    for (int mt = 0; mt < 2; mt++) {
        int c = c0 + m0 + mt * 16 + g;
#pragma unroll
        for (int nf = 0; nf < 5; nf++) {
            int n = n0 + nf * 8 + 2 * t;
            float* p = out + ((size_t)b * N_ + n) * C_ + c;
            p[0]            = acc[mt][nf][0];
            p[C_]           = acc[mt][nf][1];
            p[8]            = acc[mt][nf][2];
            p[C_ + 8]       = acc[mt][nf][3];
        }
    }
}

// ---------------------------------------------------------------------------
#define G1_SMEM (2 * 53248)
#define G2_SMEM (2 * 53248)

extern "C" void kernel_launch(void* const* d_in, const int* in_sizes, int n_in,
                              void* d_out, int out_size) {
    const float* feats = (const float*)d_in[0];  // [32, 512, 4096]
    const float* W     = (const float*)d_in[1];  // [80, 512]
    float* out         = (float*)d_out;          // [32, 80, 512]

    cudaFuncSetAttribute(gemm1_mma, cudaFuncAttributeMaxDynamicSharedMemorySize, G1_SMEM);
    cudaFuncSetAttribute(gemm2_mma, cudaFuncAttributeMaxDynamicSharedMemorySize, G2_SMEM);

    gemm1_mma<<<dim3(HW_ / 128, B_), 320, G1_SMEM>>>(feats, W);
    softmax_split<<<B_ * N_, 256>>>();
    gemm2_mma<<<dim3(C_ / 128, B_), 256, G2_SMEM>>>(feats, out);
}